// round 10
// baseline (speedup 1.0000x reference)
#include <cuda_runtime.h>
#include <cuda_bf16.h>
#include <cstdint>

// ---------------- problem constants ----------------
#define D_IN    4096
#define D_OUT   64
#define N_B     32
#define N_S     2048
#define N_LORA  16

#define TILE_M    256
#define NTHREADS  512
#define N_KCHUNK  (D_IN / 16)        // 256 k16 chunks

// ---- smem pipeline: 4 stages, one k16 chunk per stage ----
#define N_STAGES  4
#define A_ROW_B   80                  // 16 floats + 4 pad floats (16B-aligned rows)
#define A_BYTES   (TILE_M * A_ROW_B)  // 20480
#define B_OFF     A_BYTES
#define B_BYTES   4096                // 256 lanes * uint4
#define STAGE_BYTES (A_BYTES + B_BYTES)       // 24576
#define SMEM_TOTAL  (N_STAGES * STAGE_BYTES)  // 98304 (96 KB)

// ---------------- weight scratch: fragment-layout tf32 ----------------
// [lora][kchunk(256)][ntile(8)*32 + lane] -> uint4 {b_k(g), b_k(g+4), b_k(g+8), b_k(g+12)}
__device__ __align__(16) uint4 g_wfrag[(size_t)N_LORA * 256 * 256];

// ---------------- helpers ----------------
__device__ __forceinline__ uint32_t smem_u32(const void* p) {
    uint32_t a;
    asm("{ .reg .u64 t; cvta.to.shared.u64 t, %1; cvt.u32.u64 %0, t; }" : "=r"(a) : "l"(p));
    return a;
}

__device__ __forceinline__ uint32_t tf32_rna(float v) {
    uint32_t r;
    asm("cvt.rna.tf32.f32 %0, %1;" : "=r"(r) : "f"(v));
    return r;
}

// m16n8k8 tf32 MMA, fp32 accumulate
__device__ __forceinline__ void mma1688(float* c, const uint32_t* a, uint32_t b0, uint32_t b1) {
    asm volatile(
        "mma.sync.aligned.m16n8k8.row.col.f32.tf32.tf32.f32 "
        "{%0,%1,%2,%3}, {%4,%5,%6,%7}, {%8,%9}, {%0,%1,%2,%3};"
        : "+f"(c[0]), "+f"(c[1]), "+f"(c[2]), "+f"(c[3])
        : "r"(a[0]), "r"(a[1]), "r"(a[2]), "r"(a[3]), "r"(b0), "r"(b1));
}

__device__ __forceinline__ void cp_async16(uint32_t dst, const void* src) {
    asm volatile("cp.async.cg.shared.global [%0], [%1], 16;" :: "r"(dst), "l"(src) : "memory");
}

__device__ __forceinline__ float lds_f32(uint32_t a) {
    float v;
    asm volatile("ld.shared.f32 %0, [%1];" : "=f"(v) : "r"(a));
    return v;
}

// ---------------- prep: weight[lora][k][n] fp32 -> tf32 fragment scratch ----------------
__global__ void __launch_bounds__(256)
lora_prep_kernel(const float* __restrict__ w) {
    __shared__ float sw[16][68];   // [k_local][n], padded
    const int t = threadIdx.x;
    const float* src = w + (size_t)blockIdx.x * 1024;   // 16 k-rows x 64 n
    float4 v = *(const float4*)(src + t * 4);
    const int kr = t >> 4, nc = (t & 15) * 4;
    sw[kr][nc + 0] = v.x; sw[kr][nc + 1] = v.y;
    sw[kr][nc + 2] = v.z; sw[kr][nc + 3] = v.w;
    __syncthreads();

    const int nt = t >> 5, l = t & 31;
    const int g = l & 3, nl = l >> 2;
    const int n = nt * 8 + nl;
    g_wfrag[(size_t)blockIdx.x * 256 + t] = make_uint4(
        tf32_rna(sw[g + 0][n]),  tf32_rna(sw[g + 4][n]),
        tf32_rna(sw[g + 8][n]),  tf32_rna(sw[g + 12][n]));
}

// ---------------- main kernel ----------------
// issue one stage: A tile (256 rows x 16 fp32) + B frags (256 uint4) via cp.async
// 512 threads: pair of threads per A row (2 x 16B each), threads 0-255 also carry B
__device__ __forceinline__ void issue_stage(uint32_t sbase, const float* xcta,
                                            const uint4* wsrc, int s, int t) {
    const uint32_t stg = sbase + (uint32_t)(s & (N_STAGES - 1)) * STAGE_BYTES;
    const int r0 = t >> 1, seg = (t & 1) * 2;
    const float* asrc = xcta + (size_t)r0 * D_IN + s * 16 + seg * 4;
    const uint32_t adst = stg + (uint32_t)(r0 * A_ROW_B + seg * 16);
    cp_async16(adst, asrc);
    cp_async16(adst + 16, asrc + 4);
    if (t < 256)
        cp_async16(stg + B_OFF + (uint32_t)t * 16, wsrc + (size_t)s * 256 + t);
    asm volatile("cp.async.commit_group;" ::: "memory");
}

__global__ void __launch_bounds__(NTHREADS, 2)
lora_main_kernel(const float* __restrict__ x, const int* __restrict__ ids,
                 float* __restrict__ out) {
    extern __shared__ uint4 smem_buf[];
    const uint32_t sbase = smem_u32(smem_buf);
    const int t = threadIdx.x, wid = t >> 5, l = t & 31;
    const int g = l & 3, nl = l >> 2;

    const int b = blockIdx.x >> 3;
    const int mbase = (blockIdx.x & 7) * TILE_M;
    const int aid = __ldg(ids + b);
    const uint4* wsrc = g_wfrag + (size_t)aid * 256 * 256;
    const float* xcta = x + ((size_t)b * N_S + mbase) * D_IN;

    // one mtile (16 rows) x 8 ntiles per warp
    float acc[8][4];
    #pragma unroll
    for (int nt = 0; nt < 8; ++nt)
        #pragma unroll
        for (int i = 0; i < 4; ++i)
            acc[nt][i] = 0.0f;

    // prologue: fill N_STAGES-1 stages
    #pragma unroll
    for (int s = 0; s < N_STAGES - 1; ++s)
        issue_stage(sbase, xcta, wsrc, s, t);

    // per-thread A smem base: row = wid*16 + nl, col = g floats
    const uint32_t abase = sbase + (uint32_t)((wid * 16 + nl) * A_ROW_B + g * 4);

    for (int s = 0; s < N_KCHUNK; ++s) {
        asm volatile("cp.async.wait_group %0;" :: "n"(N_STAGES - 2) : "memory");
        __syncthreads();   // stage s visible; all warps done reading stage s-1's buffer
        if (s + N_STAGES - 1 < N_KCHUNK)
            issue_stage(sbase, xcta, wsrc, s + N_STAGES - 1, t);

        const uint32_t stg = (uint32_t)(s & (N_STAGES - 1)) * STAGE_BYTES;

        // ---- A fragments: fp32 -> tf32 (rna). step0 = k0..k0+7, step1 = k0+8..15 ----
        const uint32_t ab = abase + stg;
        uint32_t a0[4], a1[4];
        a0[0] = tf32_rna(lds_f32(ab));                        // (row,   g)
        a0[1] = tf32_rna(lds_f32(ab + 8 * A_ROW_B));          // (row+8, g)
        a0[2] = tf32_rna(lds_f32(ab + 16));                   // (row,   g+4)
        a0[3] = tf32_rna(lds_f32(ab + 8 * A_ROW_B + 16));     // (row+8, g+4)
        a1[0] = tf32_rna(lds_f32(ab + 32));                   // (row,   g+8)
        a1[1] = tf32_rna(lds_f32(ab + 8 * A_ROW_B + 32));     // (row+8, g+8)
        a1[2] = tf32_rna(lds_f32(ab + 48));                   // (row,   g+12)
        a1[3] = tf32_rna(lds_f32(ab + 8 * A_ROW_B + 48));     // (row+8, g+12)

        // ---- B from smem, 2 k8-step mma per ntile ----
        const uint32_t bb = sbase + stg + B_OFF + (uint32_t)(l * 16);
        #pragma unroll
        for (int nt = 0; nt < 8; ++nt) {
            uint32_t b00, b01, b10, b11;
            asm volatile("ld.shared.v4.b32 {%0,%1,%2,%3}, [%4];"
                         : "=r"(b00), "=r"(b01), "=r"(b10), "=r"(b11)
                         : "r"(bb + (uint32_t)(nt * 512)));
            mma1688(acc[nt], a0, b00, b01);  // k0..k0+7
            mma1688(acc[nt], a1, b10, b11);  // k0+8..k0+15
        }
    }

    // ---- epilogue ----
    const int row = mbase + wid * 16 + nl;
    float* o = out + ((size_t)b * N_S + row) * D_OUT + 2 * g;
    #pragma unroll
    for (int nt = 0; nt < 8; ++nt) {
        *(float2*)(o + nt * 8)             = make_float2(acc[nt][0], acc[nt][1]);
        *(float2*)(o + nt * 8 + 8 * D_OUT) = make_float2(acc[nt][2], acc[nt][3]);
    }
}

// ---------------- launch ----------------
extern "C" void kernel_launch(void* const* d_in, const int* in_sizes, int n_in,
                              void* d_out, int out_size) {
    const float* x  = (const float*)d_in[0];
    const int* ids  = (const int*)d_in[1];
    const float* w  = (const float*)d_in[2];
    float* out      = (float*)d_out;

    cudaFuncSetAttribute(lora_main_kernel,
                         cudaFuncAttributeMaxDynamicSharedMemorySize, SMEM_TOTAL);

    lora_prep_kernel<<<N_LORA * 256, 256>>>(w);
    lora_main_kernel<<<N_B * (N_S / TILE_M), NTHREADS, SMEM_TOTAL>>>(x, ids, out);
}